// round 12
// baseline (speedup 1.0000x reference)
#include <cuda_runtime.h>
#include <cuda_fp16.h>
#include <cuda_bf16.h>
#include <stdint.h>

#define N_NODES 100000
#define N_EDGES 1600000
#define DIM 128
#define SCAN_B 1024
#define SCAN_NB ((N_NODES + SCAN_B - 1) / SCAN_B)   // 98

// ---------------- scratch (no allocations allowed) ----------------
__device__ int    g_deg[N_NODES];
__device__ int    g_off[N_NODES];
__device__ int    g_cur[N_NODES];
__device__ int    g_bsums[SCAN_NB];
__device__ int    g_srcs[N_EDGES];
__device__ float  g_bufYa[(size_t)N_NODES * DIM];
__device__ __half g_bufY16a[(size_t)N_NODES * DIM];
__device__ float  g_bufYb[(size_t)N_NODES * DIM];
__device__ __half g_bufY16b[(size_t)N_NODES * DIM];
__device__ __nv_bfloat16 g_W1h[128 * 128], g_W1l[128 * 128];
__device__ __nv_bfloat16 g_Wmh[128 * 128], g_Wml[128 * 128];
__device__ __nv_bfloat16 g_W2h[128 * 64],  g_W2l[128 * 64];

// ---------------- CSR construction ----------------
__global__ void k_zero_deg() {
    int i = blockIdx.x * blockDim.x + threadIdx.x;
    if (i < N_NODES) g_deg[i] = 0;
}

__global__ void k_hist(const int* __restrict__ ei) {
    int e2 = blockIdx.x * blockDim.x + threadIdx.x;
    if (e2 < N_EDGES / 2) {
        int2 d = __ldg((const int2*)(ei + N_EDGES) + e2);
        if (d.x >= 0 && d.x < N_NODES) atomicAdd(&g_deg[d.x], 1);
        if (d.y >= 0 && d.y < N_NODES) atomicAdd(&g_deg[d.y], 1);
    }
}

__global__ void k_scan1() {
    __shared__ int s[SCAN_B];
    int tid = threadIdx.x;
    int i = blockIdx.x * SCAN_B + tid;
    int v = (i < N_NODES) ? g_deg[i] : 0;
    s[tid] = v;
    __syncthreads();
    #pragma unroll
    for (int d = 1; d < SCAN_B; d <<= 1) {
        int t = (tid >= d) ? s[tid - d] : 0;
        __syncthreads();
        s[tid] += t;
        __syncthreads();
    }
    if (i < N_NODES) g_off[i] = s[tid] - v;
    if (tid == SCAN_B - 1) g_bsums[blockIdx.x] = s[tid];
}

__global__ void k_scan2() {
    __shared__ int red[32];
    int tid = threadIdx.x;
    int v = (tid < (int)blockIdx.x && tid < SCAN_NB) ? g_bsums[tid] : 0;
    #pragma unroll
    for (int o = 16; o > 0; o >>= 1) v += __shfl_down_sync(0xffffffffu, v, o);
    if ((tid & 31) == 0) red[tid >> 5] = v;
    __syncthreads();
    if (tid < 32) {
        int r = (tid < (int)(blockDim.x >> 5)) ? red[tid] : 0;
        #pragma unroll
        for (int o = 16; o > 0; o >>= 1) r += __shfl_down_sync(0xffffffffu, r, o);
        if (tid == 0) red[0] = r;
    }
    __syncthreads();
    int base = red[0];
    int i = blockIdx.x * SCAN_B + tid;
    if (i < N_NODES) {
        int o = g_off[i] + base;
        g_off[i] = o;
        g_cur[i] = o;
    }
}

__global__ void k_scatter(const int* __restrict__ ei) {
    int e2 = blockIdx.x * blockDim.x + threadIdx.x;
    if (e2 < N_EDGES / 2) {
        int2 s = __ldg((const int2*)ei + e2);
        int2 d = __ldg((const int2*)(ei + N_EDGES) + e2);
        if (d.x >= 0 && d.x < N_NODES && s.x >= 0 && s.x < N_NODES) {
            int pos = atomicAdd(&g_cur[d.x], 1);
            g_srcs[pos] = s.x;
        }
        if (d.y >= 0 && d.y < N_NODES && s.y >= 0 && s.y < N_NODES) {
            int pos = atomicAdd(&g_cur[d.y], 1);
            g_srcs[pos] = s.y;
        }
    }
}

// ---------------- helpers ----------------
__device__ __forceinline__ unsigned cvta_s(const void* p) {
    return (unsigned)__cvta_generic_to_shared(p);
}
__device__ __forceinline__ void ldsm_x4(unsigned& r0, unsigned& r1,
                                        unsigned& r2, unsigned& r3, unsigned a) {
    asm volatile("ldmatrix.sync.aligned.m8n8.x4.shared.b16 {%0,%1,%2,%3}, [%4];"
                 : "=r"(r0), "=r"(r1), "=r"(r2), "=r"(r3) : "r"(a));
}
__device__ __forceinline__ void ldsm_x2t(unsigned& r0, unsigned& r1, unsigned a) {
    asm volatile("ldmatrix.sync.aligned.m8n8.x2.trans.shared.b16 {%0,%1}, [%2];"
                 : "=r"(r0), "=r"(r1) : "r"(a));
}
__device__ __forceinline__ void mma_bf16(float* c, unsigned a0, unsigned a1,
                                         unsigned a2, unsigned a3,
                                         unsigned b0, unsigned b1) {
    asm volatile(
        "mma.sync.aligned.m16n8k16.row.col.f32.bf16.bf16.f32 "
        "{%0,%1,%2,%3}, {%4,%5,%6,%7}, {%8,%9}, {%0,%1,%2,%3};"
        : "+f"(c[0]), "+f"(c[1]), "+f"(c[2]), "+f"(c[3])
        : "r"(a0), "r"(a1), "r"(a2), "r"(a3), "r"(b0), "r"(b1));
}
__device__ __forceinline__ unsigned pack_bf16(__nv_bfloat16 a, __nv_bfloat16 b) {
    __nv_bfloat162 p; p.x = a; p.y = b;
    return *reinterpret_cast<unsigned*>(&p);
}
__device__ __forceinline__ void bsplit(float f, __nv_bfloat16& h, __nv_bfloat16& l) {
    h = __float2bfloat16_rn(f);
    l = __float2bfloat16_rn(f - __bfloat162float(h));
}

// ---------------- W preconversion: fp32 -> bf16 hi/lo ----------------
__global__ void k_wconv(const float* __restrict__ W, __nv_bfloat16* __restrict__ Wh,
                        __nv_bfloat16* __restrict__ Wl, int n) {
    int i = blockIdx.x * blockDim.x + threadIdx.x;
    if (i < n) {
        float f = W[i];
        __nv_bfloat16 h, l;
        bsplit(f, h, l);
        Wh[i] = h; Wl[i] = l;
    }
}

// -------- shared GEMM mainloop+epilogue (64-row tile, 8 warps) --------
template <int DOUT>
__device__ __forceinline__ void gemm_body(
    const __nv_bfloat16* sAh, const __nv_bfloat16* sAl,
    const __nv_bfloat16* sWh, const __nv_bfloat16* sWl,
    int wid, int lane, int rowBase,
    float* __restrict__ Y, __half* __restrict__ Y16) {
    constexpr int LDA = 136;
    constexpr int LDB = DOUT + 8;
    constexpr int NT  = DOUT / 16;           // n-tiles per warp (8 or 4)
    int g = lane >> 2, tg = lane & 3;
    int rg = wid >> 1;                       // 0..3 -> rows 0..63
    int n0 = (wid & 1) * (DOUT / 2);
    int r0 = rg * 16;

    float acc[NT][4];
    #pragma unroll
    for (int i = 0; i < NT; ++i)
        #pragma unroll
        for (int j = 0; j < 4; ++j) acc[i][j] = 0.f;

    int arow = r0 + (lane & 15);
    int acolo = (lane >> 4) * 8;
    unsigned aH = cvta_s(sAh) + (unsigned)((arow * LDA + acolo) * 2);
    unsigned aL = cvta_s(sAl) + (unsigned)((arow * LDA + acolo) * 2);
    int brow = lane & 15;
    unsigned bH = cvta_s(sWh) + (unsigned)((brow * LDB + n0) * 2);
    unsigned bL = cvta_s(sWl) + (unsigned)((brow * LDB + n0) * 2);

    #pragma unroll
    for (int ks = 0; ks < 8; ++ks) {
        int k0 = ks * 16;
        unsigned ah0, ah1, ah2, ah3, al0, al1, al2, al3;
        ldsm_x4(ah0, ah1, ah2, ah3, aH + (unsigned)(k0 * 2));
        ldsm_x4(al0, al1, al2, al3, aL + (unsigned)(k0 * 2));
        unsigned bkoff = (unsigned)(k0 * LDB * 2);
        #pragma unroll
        for (int nt = 0; nt < NT; ++nt) {
            unsigned noff = bkoff + (unsigned)(nt * 8 * 2);
            unsigned bh0, bh1, bl0, bl1;
            ldsm_x2t(bh0, bh1, bH + noff);
            ldsm_x2t(bl0, bl1, bL + noff);
            mma_bf16(acc[nt], ah0, ah1, ah2, ah3, bh0, bh1);
            mma_bf16(acc[nt], al0, al1, al2, al3, bh0, bh1);
            mma_bf16(acc[nt], ah0, ah1, ah2, ah3, bl0, bl1);
        }
    }

    int row0 = rowBase + r0 + g;
    int row1 = row0 + 8;
    #pragma unroll
    for (int nt = 0; nt < NT; ++nt) {
        int col = n0 + nt * 8 + tg * 2;
        if (row0 < N_NODES) {
            *(float2*)(Y + (size_t)row0 * DOUT + col) = make_float2(acc[nt][0], acc[nt][1]);
            __half2 hh = __floats2half2_rn(acc[nt][0], acc[nt][1]);
            *(unsigned*)(Y16 + (size_t)row0 * DOUT + col) = *(const unsigned*)&hh;
        }
        if (row1 < N_NODES) {
            *(float2*)(Y + (size_t)row1 * DOUT + col) = make_float2(acc[nt][2], acc[nt][3]);
            __half2 hh = __floats2half2_rn(acc[nt][2], acc[nt][3]);
            *(unsigned*)(Y16 + (size_t)row1 * DOUT + col) = *(const unsigned*)&hh;
        }
    }
}

// ---------------- GEMM layer 1 (A = fp32 x, converted in prologue) ---------
__global__ void __launch_bounds__(256, 2)
k_gemm1(const float* __restrict__ X,
        const __nv_bfloat16* __restrict__ Wh, const __nv_bfloat16* __restrict__ Wl,
        float* __restrict__ Y, __half* __restrict__ Y16) {
    constexpr int DOUT = 128;
    constexpr int LDA = 136, LDB = DOUT + 8;
    extern __shared__ __nv_bfloat16 sm[];
    __nv_bfloat16* sAh = sm;
    __nv_bfloat16* sAl = sAh + 64 * LDA;
    __nv_bfloat16* sWh = sAl + 64 * LDA;
    __nv_bfloat16* sWl = sWh + 128 * LDB;

    int tid = threadIdx.x, wid = tid >> 5, lane = tid & 31;
    int rowBase = blockIdx.x * 64;

    for (int i = tid; i < 128 * (DOUT / 8); i += 256) {
        int k = i / (DOUT / 8), n8 = i % (DOUT / 8);
        uint4 vh = __ldg((const uint4*)(Wh + (size_t)k * DOUT) + n8);
        uint4 vl = __ldg((const uint4*)(Wl + (size_t)k * DOUT) + n8);
        int off = k * LDB + n8 * 8;
        *(uint4*)(sWh + off) = vh;
        *(uint4*)(sWl + off) = vl;
    }
    for (int i = tid; i < 64 * 32; i += 256) {
        int r = i >> 5, c4 = i & 31;
        int row = rowBase + r;
        float4 v = make_float4(0.f, 0.f, 0.f, 0.f);
        if (row < N_NODES)
            v = __ldg((const float4*)(X + (size_t)row * 128) + c4);
        __nv_bfloat16 h0, h1, h2, h3, l0, l1, l2, l3;
        bsplit(v.x, h0, l0); bsplit(v.y, h1, l1);
        bsplit(v.z, h2, l2); bsplit(v.w, h3, l3);
        int off = r * LDA + c4 * 4;
        *(uint2*)(sAh + off) = make_uint2(pack_bf16(h0, h1), pack_bf16(h2, h3));
        *(uint2*)(sAl + off) = make_uint2(pack_bf16(l0, l1), pack_bf16(l2, l3));
    }
    __syncthreads();
    gemm_body<128>(sAh, sAl, sWh, sWl, wid, lane, rowBase, Y, Y16);
}

// ------- FUSED: agg(prev layer, 128-dim) + bias + relu -> smem -> GEMM -----
// Input buffers (y, y16) MUST be distinct from outputs (Yo, Yo16): blocks
// gather arbitrary rows of y16 while others write Yo16.
template <int DOUT>
__global__ void __launch_bounds__(256, 2)
k_fused(const float* __restrict__ y, const __half* __restrict__ y16,
        const float* __restrict__ bias,
        const __nv_bfloat16* __restrict__ Wh, const __nv_bfloat16* __restrict__ Wl,
        float* __restrict__ Yo, __half* __restrict__ Yo16) {
    constexpr int LDA = 136, LDB = DOUT + 8;
    extern __shared__ __nv_bfloat16 sm[];
    __nv_bfloat16* sAh = sm;
    __nv_bfloat16* sAl = sAh + 64 * LDA;
    __nv_bfloat16* sWh = sAl + 64 * LDA;
    __nv_bfloat16* sWl = sWh + 128 * LDB;

    int tid = threadIdx.x, wid = tid >> 5, lane = tid & 31;
    int rowBase = blockIdx.x * 64;

    // W load first (overlaps with gathers below; consumed after sync)
    for (int i = tid; i < 128 * (DOUT / 8); i += 256) {
        int k = i / (DOUT / 8), n8 = i % (DOUT / 8);
        uint4 vh = __ldg((const uint4*)(Wh + (size_t)k * DOUT) + n8);
        uint4 vl = __ldg((const uint4*)(Wl + (size_t)k * DOUT) + n8);
        int off = k * LDB + n8 * 8;
        *(uint4*)(sWh + off) = vh;
        *(uint4*)(sWl + off) = vl;
    }

    // Phase A: aggregate 8 nodes per warp (R8 gather form), bsplit into smem
    float4 bb = __ldg((const float4*)bias + lane);
    #pragma unroll 1
    for (int j = 0; j < 8; ++j) {
        int r = wid * 8 + j;
        int node = rowBase + r;
        int off = r * LDA + lane * 4;
        if (node < N_NODES) {
            float4 acc = __ldg((const float4*)(y + (size_t)node * 128) + lane);
            float4 acc2 = make_float4(0.f, 0.f, 0.f, 0.f);
            int beg = g_off[node];
            int end = beg + g_deg[node];
            int e = beg;
            for (; e + 3 < end; e += 4) {
                int s0 = g_srcs[e],     s1 = g_srcs[e + 1];
                int s2 = g_srcs[e + 2], s3 = g_srcs[e + 3];
                uint2 u0 = __ldg((const uint2*)(y16 + (size_t)s0 * 128) + lane);
                uint2 u1 = __ldg((const uint2*)(y16 + (size_t)s1 * 128) + lane);
                uint2 u2 = __ldg((const uint2*)(y16 + (size_t)s2 * 128) + lane);
                uint2 u3 = __ldg((const uint2*)(y16 + (size_t)s3 * 128) + lane);
                float2 a0 = __half22float2(*(const __half2*)&u0.x);
                float2 b0 = __half22float2(*(const __half2*)&u0.y);
                float2 a1 = __half22float2(*(const __half2*)&u1.x);
                float2 b1 = __half22float2(*(const __half2*)&u1.y);
                float2 a2 = __half22float2(*(const __half2*)&u2.x);
                float2 b2 = __half22float2(*(const __half2*)&u2.y);
                float2 a3 = __half22float2(*(const __half2*)&u3.x);
                float2 b3 = __half22float2(*(const __half2*)&u3.y);
                acc.x  += a0.x + a1.x; acc.y  += a0.y + a1.y;
                acc.z  += b0.x + b1.x; acc.w  += b0.y + b1.y;
                acc2.x += a2.x + a3.x; acc2.y += a2.y + a3.y;
                acc2.z += b2.x + b3.x; acc2.w += b2.y + b3.y;
            }
            for (; e < end; ++e) {
                int s = g_srcs[e];
                uint2 u = __ldg((const uint2*)(y16 + (size_t)s * 128) + lane);
                float2 a = __half22float2(*(const __half2*)&u.x);
                float2 b = __half22float2(*(const __half2*)&u.y);
                acc.x += a.x; acc.y += a.y; acc.z += b.x; acc.w += b.y;
            }
            acc.x += acc2.x + bb.x; acc.y += acc2.y + bb.y;
            acc.z += acc2.z + bb.z; acc.w += acc2.w + bb.w;
            acc.x = fmaxf(acc.x, 0.f); acc.y = fmaxf(acc.y, 0.f);
            acc.z = fmaxf(acc.z, 0.f); acc.w = fmaxf(acc.w, 0.f);
            __nv_bfloat16 h0, h1, h2, h3, l0, l1, l2, l3;
            bsplit(acc.x, h0, l0); bsplit(acc.y, h1, l1);
            bsplit(acc.z, h2, l2); bsplit(acc.w, h3, l3);
            *(uint2*)(sAh + off) = make_uint2(pack_bf16(h0, h1), pack_bf16(h2, h3));
            *(uint2*)(sAl + off) = make_uint2(pack_bf16(l0, l1), pack_bf16(l2, l3));
        } else {
            *(uint2*)(sAh + off) = make_uint2(0u, 0u);
            *(uint2*)(sAl + off) = make_uint2(0u, 0u);
        }
    }
    __syncthreads();

    // Phase B: GEMM on the freshly aggregated tile
    gemm_body<DOUT>(sAh, sAl, sWh, sWl, wid, lane, rowBase, Yo, Yo16);
}

// ---------- final aggregate (64-dim) + bias -> out (R8 form) ----------
__global__ void k_agg_final(const float* __restrict__ y,
                            const __half* __restrict__ y16,
                            const float* __restrict__ bias,
                            float* __restrict__ out) {
    int gw = (blockIdx.x * blockDim.x + threadIdx.x) >> 5;
    int lane = threadIdx.x & 31;
    if (gw >= N_NODES) return;
    int beg = g_off[gw];
    int end = beg + g_deg[gw];

    float2 acc = __ldg((const float2*)(y + (size_t)gw * 64) + lane);
    float2 acc2 = make_float2(0.f, 0.f);
    int e = beg;
    for (; e + 3 < end; e += 4) {
        int s0 = g_srcs[e],     s1 = g_srcs[e + 1];
        int s2 = g_srcs[e + 2], s3 = g_srcs[e + 3];
        unsigned u0 = __ldg((const unsigned*)(y16 + (size_t)s0 * 64) + lane);
        unsigned u1 = __ldg((const unsigned*)(y16 + (size_t)s1 * 64) + lane);
        unsigned u2 = __ldg((const unsigned*)(y16 + (size_t)s2 * 64) + lane);
        unsigned u3 = __ldg((const unsigned*)(y16 + (size_t)s3 * 64) + lane);
        float2 a0 = __half22float2(*(const __half2*)&u0);
        float2 a1 = __half22float2(*(const __half2*)&u1);
        float2 a2 = __half22float2(*(const __half2*)&u2);
        float2 a3 = __half22float2(*(const __half2*)&u3);
        acc.x  += a0.x + a1.x; acc.y  += a0.y + a1.y;
        acc2.x += a2.x + a3.x; acc2.y += a2.y + a3.y;
    }
    for (; e < end; ++e) {
        int s = g_srcs[e];
        unsigned u = __ldg((const unsigned*)(y16 + (size_t)s * 64) + lane);
        float2 a = __half22float2(*(const __half2*)&u);
        acc.x += a.x; acc.y += a.y;
    }
    acc.x += acc2.x; acc.y += acc2.y;
    float2 bb = __ldg((const float2*)bias + lane);
    acc.x += bb.x; acc.y += bb.y;
    ((float2*)(out + (size_t)gw * 64))[lane] = acc;
}

// ---------------- launch ----------------
extern "C" void kernel_launch(void* const* d_in, const int* in_sizes, int n_in,
                              void* d_out, int out_size) {
    const float* x  = (const float*)d_in[0];
    const int*   ei = (const int*)d_in[1];
    const float* W1 = (const float*)d_in[2];
    const float* b1 = (const float*)d_in[3];
    const float* Wm = (const float*)d_in[4];
    const float* bm = (const float*)d_in[5];
    const float* W2 = (const float*)d_in[6];
    const float* b2 = (const float*)d_in[7];
    float* out = (float*)d_out;

    const int smem128 = (64 * 136 * 2 + 128 * 136 * 2) * 2;   // 104448
    const int smem64  = (64 * 136 * 2 + 128 * 72  * 2) * 2;   // 71680

    static bool initDone = false;
    static cudaStream_t s2 = nullptr;
    static cudaEvent_t evFork = nullptr, evJoin = nullptr;
    if (!initDone) {
        cudaFuncSetAttribute(k_gemm1,
                             cudaFuncAttributeMaxDynamicSharedMemorySize, smem128);
        cudaFuncSetAttribute(k_fused<128>,
                             cudaFuncAttributeMaxDynamicSharedMemorySize, smem128);
        cudaFuncSetAttribute(k_fused<64>,
                             cudaFuncAttributeMaxDynamicSharedMemorySize, smem64);
        cudaStreamCreateWithFlags(&s2, cudaStreamNonBlocking);
        cudaEventCreateWithFlags(&evFork, cudaEventDisableTiming);
        cudaEventCreateWithFlags(&evJoin, cudaEventDisableTiming);
        initDone = true;
    }

    float *bufYa, *bufYb; __half *bufY16a, *bufY16b;
    __nv_bfloat16 *w1h, *w1l, *wmh, *wml, *w2h, *w2l;
    cudaGetSymbolAddress((void**)&bufYa, g_bufYa);
    cudaGetSymbolAddress((void**)&bufY16a, g_bufY16a);
    cudaGetSymbolAddress((void**)&bufYb, g_bufYb);
    cudaGetSymbolAddress((void**)&bufY16b, g_bufY16b);
    cudaGetSymbolAddress((void**)&w1h, g_W1h); cudaGetSymbolAddress((void**)&w1l, g_W1l);
    cudaGetSymbolAddress((void**)&wmh, g_Wmh); cudaGetSymbolAddress((void**)&wml, g_Wml);
    cudaGetSymbolAddress((void**)&w2h, g_W2h); cudaGetSymbolAddress((void**)&w2l, g_W2l);

    const int aggBlocks = (N_NODES + 7) / 8;      // 8 warps / 256-thr block
    const int tileBlocks = (N_NODES + 63) / 64;   // 1563 (64-row tiles)

    // ---- fork: CSR build on s2, concurrent with wconv + layer-1 GEMM ----
    cudaEventRecord(evFork, 0);
    cudaStreamWaitEvent(s2, evFork, 0);

    k_zero_deg<<<(N_NODES + 255) / 256, 256, 0, s2>>>();
    k_hist<<<(N_EDGES / 2 + 255) / 256, 256, 0, s2>>>(ei);
    k_scan1<<<SCAN_NB, SCAN_B, 0, s2>>>();
    k_scan2<<<SCAN_NB, SCAN_B, 0, s2>>>();
    k_scatter<<<(N_EDGES / 2 + 255) / 256, 256, 0, s2>>>(ei);
    cudaEventRecord(evJoin, s2);

    // main stream: W conversions + layer-1 GEMM (independent of CSR)
    k_wconv<<<(128 * 128 + 255) / 256, 256>>>(W1, w1h, w1l, 128 * 128);
    k_wconv<<<(128 * 128 + 255) / 256, 256>>>(Wm, wmh, wml, 128 * 128);
    k_wconv<<<(128 * 64 + 255) / 256, 256>>>(W2, w2h, w2l, 128 * 64);
    k_gemm1<<<tileBlocks, 256, smem128>>>(x, w1h, w1l, bufYa, bufY16a);

    // join: fused agg+gemm needs CSR
    cudaStreamWaitEvent(0, evJoin, 0);

    // fused: agg1(+b1,relu) -> gemm(Wm)  => y2   (A -> B)
    k_fused<128><<<tileBlocks, 256, smem128>>>(
        bufYa, bufY16a, b1, wmh, wml, bufYb, bufY16b);

    // fused: agg2(+bm,relu) -> gemm(W2)  => y3 (64-dim)   (B -> A)
    k_fused<64><<<tileBlocks, 256, smem64>>>(
        bufYb, bufY16b, bm, w2h, w2l, bufYa, bufY16a);

    // final: out = y3 + agg(y3) + b2
    k_agg_final<<<aggBlocks, 256>>>(bufYa, bufY16a, b2, out);

    (void)in_sizes; (void)n_in; (void)out_size;
}

// round 13
// speedup vs baseline: 1.2926x; 1.2926x over previous
#include <cuda_runtime.h>
#include <cuda_fp16.h>
#include <cuda_bf16.h>
#include <stdint.h>

#define N_NODES 100000
#define N_EDGES 1600000
#define DIM 128
#define SCAN_B 1024
#define SCAN_NB ((N_NODES + SCAN_B - 1) / SCAN_B)   // 98

// ---------------- scratch (no allocations allowed) ----------------
__device__ int    g_deg[N_NODES];
__device__ int    g_off[N_NODES];
__device__ int    g_cur[N_NODES];
__device__ int    g_bsums[SCAN_NB];
__device__ int    g_srcs[N_EDGES];
__device__ float  g_bufY[(size_t)N_NODES * DIM];           // fp32 (layer 3 only)
__device__ __half g_bufY16[(size_t)N_NODES * DIM];         // fp16 GEMM out
__device__ __nv_bfloat16 g_bufHh[(size_t)N_NODES * DIM];   // h hi (next GEMM A)
__device__ __nv_bfloat16 g_bufHl[(size_t)N_NODES * DIM];   // h lo
__device__ __nv_bfloat16 g_W1h[128 * 128], g_W1l[128 * 128];
__device__ __nv_bfloat16 g_Wmh[128 * 128], g_Wml[128 * 128];
__device__ __nv_bfloat16 g_W2h[128 * 64],  g_W2l[128 * 64];

// ---------------- CSR construction ----------------
__global__ void k_zero_deg() {
    int i = blockIdx.x * blockDim.x + threadIdx.x;
    if (i < N_NODES) g_deg[i] = 0;
}

__global__ void k_hist(const int* __restrict__ ei) {
    int e = blockIdx.x * blockDim.x + threadIdx.x;
    if (e < N_EDGES) {
        int d = ei[N_EDGES + e];
        if (d >= 0 && d < N_NODES) atomicAdd(&g_deg[d], 1);
    }
}

__global__ void k_scan1() {
    __shared__ int s[SCAN_B];
    int tid = threadIdx.x;
    int i = blockIdx.x * SCAN_B + tid;
    int v = (i < N_NODES) ? g_deg[i] : 0;
    s[tid] = v;
    __syncthreads();
    #pragma unroll
    for (int d = 1; d < SCAN_B; d <<= 1) {
        int t = (tid >= d) ? s[tid - d] : 0;
        __syncthreads();
        s[tid] += t;
        __syncthreads();
    }
    if (i < N_NODES) g_off[i] = s[tid] - v;
    if (tid == SCAN_B - 1) g_bsums[blockIdx.x] = s[tid];
}

__global__ void k_scan2() {
    __shared__ int red[32];
    int tid = threadIdx.x;
    int v = (tid < (int)blockIdx.x && tid < SCAN_NB) ? g_bsums[tid] : 0;
    #pragma unroll
    for (int o = 16; o > 0; o >>= 1) v += __shfl_down_sync(0xffffffffu, v, o);
    if ((tid & 31) == 0) red[tid >> 5] = v;
    __syncthreads();
    if (tid < 32) {
        int r = (tid < (int)(blockDim.x >> 5)) ? red[tid] : 0;
        #pragma unroll
        for (int o = 16; o > 0; o >>= 1) r += __shfl_down_sync(0xffffffffu, r, o);
        if (tid == 0) red[0] = r;
    }
    __syncthreads();
    int base = red[0];
    int i = blockIdx.x * SCAN_B + tid;
    if (i < N_NODES) {
        int o = g_off[i] + base;
        g_off[i] = o;
        g_cur[i] = o;
    }
}

__global__ void k_scatter(const int* __restrict__ ei) {
    int e = blockIdx.x * blockDim.x + threadIdx.x;
    if (e < N_EDGES) {
        int d = ei[N_EDGES + e];
        int s = ei[e];
        if (d >= 0 && d < N_NODES && s >= 0 && s < N_NODES) {
            int pos = atomicAdd(&g_cur[d], 1);
            g_srcs[pos] = s;
        }
    }
}

// ---------------- helpers ----------------
__device__ __forceinline__ unsigned cvta_s(const void* p) {
    return (unsigned)__cvta_generic_to_shared(p);
}
__device__ __forceinline__ void ldsm_x4(unsigned& r0, unsigned& r1,
                                        unsigned& r2, unsigned& r3, unsigned a) {
    asm volatile("ldmatrix.sync.aligned.m8n8.x4.shared.b16 {%0,%1,%2,%3}, [%4];"
                 : "=r"(r0), "=r"(r1), "=r"(r2), "=r"(r3) : "r"(a));
}
__device__ __forceinline__ void ldsm_x2t(unsigned& r0, unsigned& r1, unsigned a) {
    asm volatile("ldmatrix.sync.aligned.m8n8.x2.trans.shared.b16 {%0,%1}, [%2];"
                 : "=r"(r0), "=r"(r1) : "r"(a));
}
__device__ __forceinline__ void mma_bf16(float* c, unsigned a0, unsigned a1,
                                         unsigned a2, unsigned a3,
                                         unsigned b0, unsigned b1) {
    asm volatile(
        "mma.sync.aligned.m16n8k16.row.col.f32.bf16.bf16.f32 "
        "{%0,%1,%2,%3}, {%4,%5,%6,%7}, {%8,%9}, {%0,%1,%2,%3};"
        : "+f"(c[0]), "+f"(c[1]), "+f"(c[2]), "+f"(c[3])
        : "r"(a0), "r"(a1), "r"(a2), "r"(a3), "r"(b0), "r"(b1));
}
__device__ __forceinline__ unsigned pack_bf16(__nv_bfloat16 a, __nv_bfloat16 b) {
    __nv_bfloat162 p; p.x = a; p.y = b;
    return *reinterpret_cast<unsigned*>(&p);
}
__device__ __forceinline__ void bsplit(float f, __nv_bfloat16& h, __nv_bfloat16& l) {
    h = __float2bfloat16_rn(f);
    l = __float2bfloat16_rn(f - __bfloat162float(h));
}

// ---------------- W preconversion: fp32 -> bf16 hi/lo ----------------
__global__ void k_wconv(const float* __restrict__ W, __nv_bfloat16* __restrict__ Wh,
                        __nv_bfloat16* __restrict__ Wl, int n) {
    int i = blockIdx.x * blockDim.x + threadIdx.x;
    if (i < n) {
        float f = W[i];
        __nv_bfloat16 h, l;
        bsplit(f, h, l);
        Wh[i] = h; Wl[i] = l;
    }
}

// ---------------- GEMM (tensor core, bf16-split): Y = A[N,128] @ W[128,DOUT]
// WRITE32: also write fp32 Y (only needed for the final layer).
template <int DOUT, bool A_SPLIT, bool WRITE32>
__global__ void __launch_bounds__(256, 2)
k_gemm_tc(const float* __restrict__ X,
          const __nv_bfloat16* __restrict__ Xh, const __nv_bfloat16* __restrict__ Xl,
          const __nv_bfloat16* __restrict__ Wh, const __nv_bfloat16* __restrict__ Wl,
          float* __restrict__ Y, __half* __restrict__ Y16) {
    constexpr int TROWS = (DOUT == 128) ? 64 : 128;
    constexpr int LDA = 136;
    constexpr int LDB = DOUT + 8;
    extern __shared__ __nv_bfloat16 sm[];
    __nv_bfloat16* sAh = sm;
    __nv_bfloat16* sAl = sAh + TROWS * LDA;
    __nv_bfloat16* sWh = sAl + TROWS * LDA;
    __nv_bfloat16* sWl = sWh + 128 * LDB;

    int tid = threadIdx.x, wid = tid >> 5, lane = tid & 31;
    int g = lane >> 2, tg = lane & 3;
    int rowBase = blockIdx.x * TROWS;

    if constexpr (A_SPLIT) {
        for (int i = tid; i < TROWS * 16; i += 256) {
            int r = i >> 4, c8 = i & 15;
            int row = rowBase + r;
            uint4 vh = make_uint4(0, 0, 0, 0), vl = make_uint4(0, 0, 0, 0);
            if (row < N_NODES) {
                vh = __ldg((const uint4*)(Xh + (size_t)row * 128) + c8);
                vl = __ldg((const uint4*)(Xl + (size_t)row * 128) + c8);
            }
            int off = r * LDA + c8 * 8;
            *(uint4*)(sAh + off) = vh;
            *(uint4*)(sAl + off) = vl;
        }
    } else {
        for (int i = tid; i < TROWS * 32; i += 256) {
            int r = i >> 5, c4 = i & 31;
            int row = rowBase + r;
            float4 v = make_float4(0.f, 0.f, 0.f, 0.f);
            if (row < N_NODES)
                v = __ldg((const float4*)(X + (size_t)row * 128) + c4);
            __nv_bfloat16 h0, h1, h2, h3, l0, l1, l2, l3;
            bsplit(v.x, h0, l0); bsplit(v.y, h1, l1);
            bsplit(v.z, h2, l2); bsplit(v.w, h3, l3);
            int off = r * LDA + c4 * 4;
            *(uint2*)(sAh + off) = make_uint2(pack_bf16(h0, h1), pack_bf16(h2, h3));
            *(uint2*)(sAl + off) = make_uint2(pack_bf16(l0, l1), pack_bf16(l2, l3));
        }
    }
    for (int i = tid; i < 128 * (DOUT / 8); i += 256) {
        int k = i / (DOUT / 8), n8 = i % (DOUT / 8);
        uint4 vh = __ldg((const uint4*)(Wh + (size_t)k * DOUT) + n8);
        uint4 vl = __ldg((const uint4*)(Wl + (size_t)k * DOUT) + n8);
        int off = k * LDB + n8 * 8;
        *(uint4*)(sWh + off) = vh;
        *(uint4*)(sWl + off) = vl;
    }
    __syncthreads();

    int rg, n0;
    if constexpr (DOUT == 128) { rg = wid >> 1; n0 = (wid & 1) * 64; }
    else                       { rg = wid;      n0 = 0; }
    int r0 = rg * 16;

    float acc[8][4];
    #pragma unroll
    for (int i = 0; i < 8; ++i)
        #pragma unroll
        for (int j = 0; j < 4; ++j) acc[i][j] = 0.f;

    int arow = r0 + (lane & 15);
    int acolo = (lane >> 4) * 8;
    unsigned aH = cvta_s(sAh) + (unsigned)((arow * LDA + acolo) * 2);
    unsigned aL = cvta_s(sAl) + (unsigned)((arow * LDA + acolo) * 2);
    int brow = lane & 15;
    unsigned bH = cvta_s(sWh) + (unsigned)((brow * LDB + n0) * 2);
    unsigned bL = cvta_s(sWl) + (unsigned)((brow * LDB + n0) * 2);

    #pragma unroll
    for (int ks = 0; ks < 8; ++ks) {
        int k0 = ks * 16;
        unsigned ah0, ah1, ah2, ah3, al0, al1, al2, al3;
        ldsm_x4(ah0, ah1, ah2, ah3, aH + (unsigned)(k0 * 2));
        ldsm_x4(al0, al1, al2, al3, aL + (unsigned)(k0 * 2));
        unsigned bkoff = (unsigned)(k0 * LDB * 2);
        #pragma unroll
        for (int nt = 0; nt < 8; ++nt) {
            unsigned noff = bkoff + (unsigned)(nt * 8 * 2);
            unsigned bh0, bh1, bl0, bl1;
            ldsm_x2t(bh0, bh1, bH + noff);
            ldsm_x2t(bl0, bl1, bL + noff);
            mma_bf16(acc[nt], ah0, ah1, ah2, ah3, bh0, bh1);
            mma_bf16(acc[nt], al0, al1, al2, al3, bh0, bh1);
            mma_bf16(acc[nt], ah0, ah1, ah2, ah3, bl0, bl1);
        }
    }

    int row0 = rowBase + r0 + g;
    int row1 = row0 + 8;
    #pragma unroll
    for (int nt = 0; nt < 8; ++nt) {
        int col = n0 + nt * 8 + tg * 2;
        if (row0 < N_NODES) {
            if constexpr (WRITE32)
                *(float2*)(Y + (size_t)row0 * DOUT + col) = make_float2(acc[nt][0], acc[nt][1]);
            __half2 hh = __floats2half2_rn(acc[nt][0], acc[nt][1]);
            *(unsigned*)(Y16 + (size_t)row0 * DOUT + col) = *(const unsigned*)&hh;
        }
        if (row1 < N_NODES) {
            if constexpr (WRITE32)
                *(float2*)(Y + (size_t)row1 * DOUT + col) = make_float2(acc[nt][2], acc[nt][3]);
            __half2 hh = __floats2half2_rn(acc[nt][2], acc[nt][3]);
            *(unsigned*)(Y16 + (size_t)row1 * DOUT + col) = *(const unsigned*)&hh;
        }
    }
}

// ---------- fused aggregate + bias (+relu) (R8 form) -----------------------
// 128-dim: self term read from fp16 mirror (one more fp16-rounded row among
// ~17; error impact negligible). 64-dim (final): self term fp32.
template <int D, bool RELU, bool SPLIT_OUT>
__global__ void k_agg_post(const float* __restrict__ y,
                           const __half* __restrict__ y16,
                           const float* __restrict__ bias,
                           float* __restrict__ out,
                           __nv_bfloat16* __restrict__ outh,
                           __nv_bfloat16* __restrict__ outl) {
    int gw = (blockIdx.x * blockDim.x + threadIdx.x) >> 5;
    int lane = threadIdx.x & 31;
    if (gw >= N_NODES) return;
    int beg = g_off[gw];
    int end = beg + g_deg[gw];

    if constexpr (D == 128) {
        uint2 su = __ldg((const uint2*)(y16 + (size_t)gw * 128) + lane);
        float2 sa = __half22float2(*(const __half2*)&su.x);
        float2 sb = __half22float2(*(const __half2*)&su.y);
        float4 acc = make_float4(sa.x, sa.y, sb.x, sb.y);
        float4 acc2 = make_float4(0.f, 0.f, 0.f, 0.f);
        int e = beg;
        for (; e + 3 < end; e += 4) {
            int s0 = g_srcs[e],     s1 = g_srcs[e + 1];
            int s2 = g_srcs[e + 2], s3 = g_srcs[e + 3];
            uint2 u0 = __ldg((const uint2*)(y16 + (size_t)s0 * 128) + lane);
            uint2 u1 = __ldg((const uint2*)(y16 + (size_t)s1 * 128) + lane);
            uint2 u2 = __ldg((const uint2*)(y16 + (size_t)s2 * 128) + lane);
            uint2 u3 = __ldg((const uint2*)(y16 + (size_t)s3 * 128) + lane);
            float2 a0 = __half22float2(*(const __half2*)&u0.x);
            float2 b0 = __half22float2(*(const __half2*)&u0.y);
            float2 a1 = __half22float2(*(const __half2*)&u1.x);
            float2 b1 = __half22float2(*(const __half2*)&u1.y);
            float2 a2 = __half22float2(*(const __half2*)&u2.x);
            float2 b2 = __half22float2(*(const __half2*)&u2.y);
            float2 a3 = __half22float2(*(const __half2*)&u3.x);
            float2 b3 = __half22float2(*(const __half2*)&u3.y);
            acc.x  += a0.x + a1.x; acc.y  += a0.y + a1.y;
            acc.z  += b0.x + b1.x; acc.w  += b0.y + b1.y;
            acc2.x += a2.x + a3.x; acc2.y += a2.y + a3.y;
            acc2.z += b2.x + b3.x; acc2.w += b2.y + b3.y;
        }
        for (; e < end; ++e) {
            int s = g_srcs[e];
            uint2 u = __ldg((const uint2*)(y16 + (size_t)s * 128) + lane);
            float2 a = __half22float2(*(const __half2*)&u.x);
            float2 b = __half22float2(*(const __half2*)&u.y);
            acc.x += a.x; acc.y += a.y; acc.z += b.x; acc.w += b.y;
        }
        acc.x += acc2.x; acc.y += acc2.y; acc.z += acc2.z; acc.w += acc2.w;
        float4 bb = __ldg((const float4*)bias + lane);
        acc.x += bb.x; acc.y += bb.y; acc.z += bb.z; acc.w += bb.w;
        if (RELU) {
            acc.x = fmaxf(acc.x, 0.f); acc.y = fmaxf(acc.y, 0.f);
            acc.z = fmaxf(acc.z, 0.f); acc.w = fmaxf(acc.w, 0.f);
        }
        if constexpr (SPLIT_OUT) {
            __nv_bfloat16 h0, h1, h2, h3, l0, l1, l2, l3;
            bsplit(acc.x, h0, l0); bsplit(acc.y, h1, l1);
            bsplit(acc.z, h2, l2); bsplit(acc.w, h3, l3);
            ((uint2*)(outh + (size_t)gw * 128))[lane] =
                make_uint2(pack_bf16(h0, h1), pack_bf16(h2, h3));
            ((uint2*)(outl + (size_t)gw * 128))[lane] =
                make_uint2(pack_bf16(l0, l1), pack_bf16(l2, l3));
        } else {
            ((float4*)(out + (size_t)gw * 128))[lane] = acc;
        }
    } else {
        float2 acc = __ldg((const float2*)(y + (size_t)gw * 64) + lane);
        float2 acc2 = make_float2(0.f, 0.f);
        int e = beg;
        for (; e + 3 < end; e += 4) {
            int s0 = g_srcs[e],     s1 = g_srcs[e + 1];
            int s2 = g_srcs[e + 2], s3 = g_srcs[e + 3];
            unsigned u0 = __ldg((const unsigned*)(y16 + (size_t)s0 * 64) + lane);
            unsigned u1 = __ldg((const unsigned*)(y16 + (size_t)s1 * 64) + lane);
            unsigned u2 = __ldg((const unsigned*)(y16 + (size_t)s2 * 64) + lane);
            unsigned u3 = __ldg((const unsigned*)(y16 + (size_t)s3 * 64) + lane);
            float2 a0 = __half22float2(*(const __half2*)&u0);
            float2 a1 = __half22float2(*(const __half2*)&u1);
            float2 a2 = __half22float2(*(const __half2*)&u2);
            float2 a3 = __half22float2(*(const __half2*)&u3);
            acc.x  += a0.x + a1.x; acc.y  += a0.y + a1.y;
            acc2.x += a2.x + a3.x; acc2.y += a2.y + a3.y;
        }
        for (; e < end; ++e) {
            int s = g_srcs[e];
            unsigned u = __ldg((const unsigned*)(y16 + (size_t)s * 64) + lane);
            float2 a = __half22float2(*(const __half2*)&u);
            acc.x += a.x; acc.y += a.y;
        }
        acc.x += acc2.x; acc.y += acc2.y;
        float2 bb = __ldg((const float2*)bias + lane);
        acc.x += bb.x; acc.y += bb.y;
        if (RELU) { acc.x = fmaxf(acc.x, 0.f); acc.y = fmaxf(acc.y, 0.f); }
        ((float2*)(out + (size_t)gw * 64))[lane] = acc;
    }
}

// ---------------- launch ----------------
extern "C" void kernel_launch(void* const* d_in, const int* in_sizes, int n_in,
                              void* d_out, int out_size) {
    const float* x  = (const float*)d_in[0];
    const int*   ei = (const int*)d_in[1];
    const float* W1 = (const float*)d_in[2];
    const float* b1 = (const float*)d_in[3];
    const float* Wm = (const float*)d_in[4];
    const float* bm = (const float*)d_in[5];
    const float* W2 = (const float*)d_in[6];
    const float* b2 = (const float*)d_in[7];
    float* out = (float*)d_out;

    const int smem128 = (64 * 136 * 2 + 128 * 136 * 2) * 2;   // 104448
    const int smem64  = (128 * 136 * 2 + 128 * 72 * 2) * 2;   // 106496

    static bool initDone = false;
    static cudaStream_t s2 = nullptr;
    static cudaEvent_t evFork = nullptr, evJoin = nullptr;
    if (!initDone) {
        cudaFuncSetAttribute((const void*)k_gemm_tc<128, false, false>,
                             cudaFuncAttributeMaxDynamicSharedMemorySize, smem128);
        cudaFuncSetAttribute((const void*)k_gemm_tc<128, true, false>,
                             cudaFuncAttributeMaxDynamicSharedMemorySize, smem128);
        cudaFuncSetAttribute((const void*)k_gemm_tc<64, true, true>,
                             cudaFuncAttributeMaxDynamicSharedMemorySize, smem64);
        cudaStreamCreateWithFlags(&s2, cudaStreamNonBlocking);
        cudaEventCreateWithFlags(&evFork, cudaEventDisableTiming);
        cudaEventCreateWithFlags(&evJoin, cudaEventDisableTiming);
        initDone = true;
    }

    float* bufY = nullptr; __half* bufY16 = nullptr;
    __nv_bfloat16 *bufHh = nullptr, *bufHl = nullptr;
    __nv_bfloat16 *w1h, *w1l, *wmh, *wml, *w2h, *w2l;
    cudaGetSymbolAddress((void**)&bufY, g_bufY);
    cudaGetSymbolAddress((void**)&bufY16, g_bufY16);
    cudaGetSymbolAddress((void**)&bufHh, g_bufHh);
    cudaGetSymbolAddress((void**)&bufHl, g_bufHl);
    cudaGetSymbolAddress((void**)&w1h, g_W1h); cudaGetSymbolAddress((void**)&w1l, g_W1l);
    cudaGetSymbolAddress((void**)&wmh, g_Wmh); cudaGetSymbolAddress((void**)&wml, g_Wml);
    cudaGetSymbolAddress((void**)&w2h, g_W2h); cudaGetSymbolAddress((void**)&w2l, g_W2l);

    const int aggBlocks = (N_NODES + 7) / 8;
    const int gemmB128  = (N_NODES + 63) / 64;
    const int gemmB64   = (N_NODES + 127) / 128;

    // ---- fork: Wm/W2 conversion + CSR build on s2 (exact R8 layout) ----
    cudaEventRecord(evFork, 0);
    cudaStreamWaitEvent(s2, evFork, 0);

    k_wconv<<<(128 * 128 + 255) / 256, 256, 0, s2>>>(Wm, wmh, wml, 128 * 128);
    k_wconv<<<(128 * 64 + 255) / 256, 256, 0, s2>>>(W2, w2h, w2l, 128 * 64);
    k_zero_deg<<<(N_NODES + 255) / 256, 256, 0, s2>>>();
    k_hist<<<(N_EDGES + 255) / 256, 256, 0, s2>>>(ei);
    k_scan1<<<SCAN_NB, SCAN_B, 0, s2>>>();
    k_scan2<<<SCAN_NB, SCAN_B, 0, s2>>>();
    k_scatter<<<(N_EDGES + 255) / 256, 256, 0, s2>>>(ei);
    cudaEventRecord(evJoin, s2);

    // main stream: W1 conversion + layer-1 GEMM (fp16-only output)
    k_wconv<<<(128 * 128 + 255) / 256, 256>>>(W1, w1h, w1l, 128 * 128);
    k_gemm_tc<128, false, false><<<gemmB128, 256, smem128>>>(
        x, nullptr, nullptr, w1h, w1l, bufY, bufY16);

    cudaStreamWaitEvent(0, evJoin, 0);

    // layer 1 agg (self from fp16) -> bf16 split h
    k_agg_post<128, true, true><<<aggBlocks, 256>>>(
        bufY, bufY16, b1, nullptr, bufHh, bufHl);

    // layer 2 (fp16-only output)
    k_gemm_tc<128, true, false><<<gemmB128, 256, smem128>>>(
        nullptr, bufHh, bufHl, wmh, wml, bufY, bufY16);
    k_agg_post<128, true, true><<<aggBlocks, 256>>>(
        bufY, bufY16, bm, nullptr, bufHh, bufHl);

    // layer 3 (64-dim, fp32 + fp16 output for final precision)
    k_gemm_tc<64, true, true><<<gemmB64, 256, smem64>>>(
        nullptr, bufHh, bufHl, w2h, w2l, bufY, bufY16);
    k_agg_post<64, false, false><<<aggBlocks, 256>>>(
        bufY, bufY16, b2, out, nullptr, nullptr);

    (void)in_sizes; (void)n_in; (void)out_size;
}

// round 14
// speedup vs baseline: 1.5235x; 1.1786x over previous
#include <cuda_runtime.h>
#include <cuda_fp16.h>
#include <cuda_bf16.h>
#include <stdint.h>

#define N_NODES 100000
#define N_EDGES 1600000
#define DIM 128
#define SCAN_B 1024
#define SCAN_NB ((N_NODES + SCAN_B - 1) / SCAN_B)   // 98
#define PGRID 296   // persistent GEMM grid: 2 CTAs/SM floor for 148-152 SMs

// ---------------- scratch (no allocations allowed) ----------------
__device__ int    g_deg[N_NODES];
__device__ int    g_off[N_NODES];
__device__ int    g_cur[N_NODES];
__device__ int    g_bsums[SCAN_NB];
__device__ int    g_srcs[N_EDGES];
__device__ float  g_bufY[(size_t)N_NODES * DIM];     // fp32 (layer 3 only)
__device__ __half g_bufY16[(size_t)N_NODES * DIM];   // fp16 GEMM out (gather src)
__device__ __half g_bufHf[(size_t)N_NODES * DIM];    // fp16 h (next GEMM A)
__device__ __nv_bfloat16 g_W1h[128 * 128], g_W1l[128 * 128];
__device__ __nv_bfloat16 g_Wmh[128 * 128], g_Wml[128 * 128];
__device__ __nv_bfloat16 g_W2h[128 * 64],  g_W2l[128 * 64];

// ---------------- CSR construction ----------------
__global__ void k_zero_deg() {
    int i = blockIdx.x * blockDim.x + threadIdx.x;
    if (i < N_NODES) g_deg[i] = 0;
}

__global__ void k_hist(const int* __restrict__ ei) {
    int e = blockIdx.x * blockDim.x + threadIdx.x;
    if (e < N_EDGES) {
        int d = ei[N_EDGES + e];
        if (d >= 0 && d < N_NODES) atomicAdd(&g_deg[d], 1);
    }
}

__global__ void k_scan1() {
    __shared__ int s[SCAN_B];
    int tid = threadIdx.x;
    int i = blockIdx.x * SCAN_B + tid;
    int v = (i < N_NODES) ? g_deg[i] : 0;
    s[tid] = v;
    __syncthreads();
    #pragma unroll
    for (int d = 1; d < SCAN_B; d <<= 1) {
        int t = (tid >= d) ? s[tid - d] : 0;
        __syncthreads();
        s[tid] += t;
        __syncthreads();
    }
    if (i < N_NODES) g_off[i] = s[tid] - v;
    if (tid == SCAN_B - 1) g_bsums[blockIdx.x] = s[tid];
}

__global__ void k_scan2() {
    __shared__ int red[32];
    int tid = threadIdx.x;
    int v = (tid < (int)blockIdx.x && tid < SCAN_NB) ? g_bsums[tid] : 0;
    #pragma unroll
    for (int o = 16; o > 0; o >>= 1) v += __shfl_down_sync(0xffffffffu, v, o);
    if ((tid & 31) == 0) red[tid >> 5] = v;
    __syncthreads();
    if (tid < 32) {
        int r = (tid < (int)(blockDim.x >> 5)) ? red[tid] : 0;
        #pragma unroll
        for (int o = 16; o > 0; o >>= 1) r += __shfl_down_sync(0xffffffffu, r, o);
        if (tid == 0) red[0] = r;
    }
    __syncthreads();
    int base = red[0];
    int i = blockIdx.x * SCAN_B + tid;
    if (i < N_NODES) {
        int o = g_off[i] + base;
        g_off[i] = o;
        g_cur[i] = o;
    }
}

__global__ void k_scatter(const int* __restrict__ ei) {
    int e = blockIdx.x * blockDim.x + threadIdx.x;
    if (e < N_EDGES) {
        int d = ei[N_EDGES + e];
        int s = ei[e];
        if (d >= 0 && d < N_NODES && s >= 0 && s < N_NODES) {
            int pos = atomicAdd(&g_cur[d], 1);
            g_srcs[pos] = s;
        }
    }
}

// ---------------- helpers ----------------
__device__ __forceinline__ unsigned cvta_s(const void* p) {
    return (unsigned)__cvta_generic_to_shared(p);
}
__device__ __forceinline__ void ldsm_x4(unsigned& r0, unsigned& r1,
                                        unsigned& r2, unsigned& r3, unsigned a) {
    asm volatile("ldmatrix.sync.aligned.m8n8.x4.shared.b16 {%0,%1,%2,%3}, [%4];"
                 : "=r"(r0), "=r"(r1), "=r"(r2), "=r"(r3) : "r"(a));
}
__device__ __forceinline__ void ldsm_x2t(unsigned& r0, unsigned& r1, unsigned a) {
    asm volatile("ldmatrix.sync.aligned.m8n8.x2.trans.shared.b16 {%0,%1}, [%2];"
                 : "=r"(r0), "=r"(r1) : "r"(a));
}
__device__ __forceinline__ void mma_bf16(float* c, unsigned a0, unsigned a1,
                                         unsigned a2, unsigned a3,
                                         unsigned b0, unsigned b1) {
    asm volatile(
        "mma.sync.aligned.m16n8k16.row.col.f32.bf16.bf16.f32 "
        "{%0,%1,%2,%3}, {%4,%5,%6,%7}, {%8,%9}, {%0,%1,%2,%3};"
        : "+f"(c[0]), "+f"(c[1]), "+f"(c[2]), "+f"(c[3])
        : "r"(a0), "r"(a1), "r"(a2), "r"(a3), "r"(b0), "r"(b1));
}
__device__ __forceinline__ unsigned pack_bf16(__nv_bfloat16 a, __nv_bfloat16 b) {
    __nv_bfloat162 p; p.x = a; p.y = b;
    return *reinterpret_cast<unsigned*>(&p);
}
__device__ __forceinline__ void bsplit(float f, __nv_bfloat16& h, __nv_bfloat16& l) {
    h = __float2bfloat16_rn(f);
    l = __float2bfloat16_rn(f - __bfloat162float(h));
}

// ---------------- W preconversion: fp32 -> bf16 hi/lo ----------------
__global__ void k_wconv(const float* __restrict__ W, __nv_bfloat16* __restrict__ Wh,
                        __nv_bfloat16* __restrict__ Wl, int n) {
    int i = blockIdx.x * blockDim.x + threadIdx.x;
    if (i < n) {
        float f = W[i];
        __nv_bfloat16 h, l;
        bsplit(f, h, l);
        Wh[i] = h; Wl[i] = l;
    }
}

// -------- GEMM mainloop+epilogue for one 64/128-row tile (8 warps) --------
template <int DOUT, bool WRITE32>
__device__ __forceinline__ void gemm_body(
    const __nv_bfloat16* sAh, const __nv_bfloat16* sAl,
    const __nv_bfloat16* sWh, const __nv_bfloat16* sWl,
    int wid, int lane, int rowBase,
    float* __restrict__ Y, __half* __restrict__ Y16) {
    constexpr int LDA = 136;
    constexpr int LDB = DOUT + 8;
    int g = lane >> 2, tg = lane & 3;
    int rg, n0;
    if constexpr (DOUT == 128) { rg = wid >> 1; n0 = (wid & 1) * 64; }
    else                       { rg = wid;      n0 = 0; }
    int r0 = rg * 16;

    float acc[8][4];
    #pragma unroll
    for (int i = 0; i < 8; ++i)
        #pragma unroll
        for (int j = 0; j < 4; ++j) acc[i][j] = 0.f;

    int arow = r0 + (lane & 15);
    int acolo = (lane >> 4) * 8;
    unsigned aH = cvta_s(sAh) + (unsigned)((arow * LDA + acolo) * 2);
    unsigned aL = cvta_s(sAl) + (unsigned)((arow * LDA + acolo) * 2);
    int brow = lane & 15;
    unsigned bH = cvta_s(sWh) + (unsigned)((brow * LDB + n0) * 2);
    unsigned bL = cvta_s(sWl) + (unsigned)((brow * LDB + n0) * 2);

    #pragma unroll
    for (int ks = 0; ks < 8; ++ks) {
        int k0 = ks * 16;
        unsigned ah0, ah1, ah2, ah3, al0, al1, al2, al3;
        ldsm_x4(ah0, ah1, ah2, ah3, aH + (unsigned)(k0 * 2));
        ldsm_x4(al0, al1, al2, al3, aL + (unsigned)(k0 * 2));
        unsigned bkoff = (unsigned)(k0 * LDB * 2);
        #pragma unroll
        for (int nt = 0; nt < 8; ++nt) {
            unsigned noff = bkoff + (unsigned)(nt * 8 * 2);
            unsigned bh0, bh1, bl0, bl1;
            ldsm_x2t(bh0, bh1, bH + noff);
            ldsm_x2t(bl0, bl1, bL + noff);
            mma_bf16(acc[nt], ah0, ah1, ah2, ah3, bh0, bh1);
            mma_bf16(acc[nt], al0, al1, al2, al3, bh0, bh1);
            mma_bf16(acc[nt], ah0, ah1, ah2, ah3, bl0, bl1);
        }
    }

    int row0 = rowBase + r0 + g;
    int row1 = row0 + 8;
    #pragma unroll
    for (int nt = 0; nt < 8; ++nt) {
        int col = n0 + nt * 8 + tg * 2;
        if (row0 < N_NODES) {
            if constexpr (WRITE32)
                *(float2*)(Y + (size_t)row0 * DOUT + col) = make_float2(acc[nt][0], acc[nt][1]);
            __half2 hh = __floats2half2_rn(acc[nt][0], acc[nt][1]);
            *(unsigned*)(Y16 + (size_t)row0 * DOUT + col) = *(const unsigned*)&hh;
        }
        if (row1 < N_NODES) {
            if constexpr (WRITE32)
                *(float2*)(Y + (size_t)row1 * DOUT + col) = make_float2(acc[nt][2], acc[nt][3]);
            __half2 hh = __floats2half2_rn(acc[nt][2], acc[nt][3]);
            *(unsigned*)(Y16 + (size_t)row1 * DOUT + col) = *(const unsigned*)&hh;
        }
    }
}

// ---------------- Persistent GEMM: Y = A[N,128] @ W[128,DOUT] --------------
// W loaded into smem ONCE per CTA; loop over row tiles (stride gridDim.x).
// A_FP16: A from fp16 h buffer (exact fp16->bf16hi+lo split); else fp32 X.
template <int DOUT, bool A_FP16, bool WRITE32>
__global__ void __launch_bounds__(256, 2)
k_gemm_p(const float* __restrict__ X, const __half* __restrict__ Xf,
         const __nv_bfloat16* __restrict__ Wh, const __nv_bfloat16* __restrict__ Wl,
         float* __restrict__ Y, __half* __restrict__ Y16) {
    constexpr int TROWS = (DOUT == 128) ? 64 : 128;
    constexpr int LDA = 136;
    constexpr int LDB = DOUT + 8;
    extern __shared__ __nv_bfloat16 sm[];
    __nv_bfloat16* sAh = sm;
    __nv_bfloat16* sAl = sAh + TROWS * LDA;
    __nv_bfloat16* sWh = sAl + TROWS * LDA;
    __nv_bfloat16* sWl = sWh + 128 * LDB;

    int tid = threadIdx.x, wid = tid >> 5, lane = tid & 31;

    // W load once
    for (int i = tid; i < 128 * (DOUT / 8); i += 256) {
        int k = i / (DOUT / 8), n8 = i % (DOUT / 8);
        uint4 vh = __ldg((const uint4*)(Wh + (size_t)k * DOUT) + n8);
        uint4 vl = __ldg((const uint4*)(Wl + (size_t)k * DOUT) + n8);
        int off = k * LDB + n8 * 8;
        *(uint4*)(sWh + off) = vh;
        *(uint4*)(sWl + off) = vl;
    }

    const int numTiles = (N_NODES + TROWS - 1) / TROWS;
    for (int t = blockIdx.x; t < numTiles; t += gridDim.x) {
        int rowBase = t * TROWS;
        __syncthreads();   // sA free (prev mainloop done) + first-iter W ready
        if constexpr (A_FP16) {
            for (int i = tid; i < TROWS * 32; i += 256) {
                int r = i >> 5, c4 = i & 31;
                int row = rowBase + r;
                uint2 u = make_uint2(0, 0);
                if (row < N_NODES)
                    u = __ldg((const uint2*)(Xf + (size_t)row * 128) + c4);
                float2 f0 = __half22float2(*(const __half2*)&u.x);
                float2 f1 = __half22float2(*(const __half2*)&u.y);
                __nv_bfloat16 h0, h1, h2, h3, l0, l1, l2, l3;
                bsplit(f0.x, h0, l0); bsplit(f0.y, h1, l1);
                bsplit(f1.x, h2, l2); bsplit(f1.y, h3, l3);
                int off = r * LDA + c4 * 4;
                *(uint2*)(sAh + off) = make_uint2(pack_bf16(h0, h1), pack_bf16(h2, h3));
                *(uint2*)(sAl + off) = make_uint2(pack_bf16(l0, l1), pack_bf16(l2, l3));
            }
        } else {
            for (int i = tid; i < TROWS * 32; i += 256) {
                int r = i >> 5, c4 = i & 31;
                int row = rowBase + r;
                float4 v = make_float4(0.f, 0.f, 0.f, 0.f);
                if (row < N_NODES)
                    v = __ldg((const float4*)(X + (size_t)row * 128) + c4);
                __nv_bfloat16 h0, h1, h2, h3, l0, l1, l2, l3;
                bsplit(v.x, h0, l0); bsplit(v.y, h1, l1);
                bsplit(v.z, h2, l2); bsplit(v.w, h3, l3);
                int off = r * LDA + c4 * 4;
                *(uint2*)(sAh + off) = make_uint2(pack_bf16(h0, h1), pack_bf16(h2, h3));
                *(uint2*)(sAl + off) = make_uint2(pack_bf16(l0, l1), pack_bf16(l2, l3));
            }
        }
        __syncthreads();
        gemm_body<DOUT, WRITE32>(sAh, sAl, sWh, sWl, wid, lane, rowBase, Y, Y16);
    }
}

// ---------- fused aggregate + bias (+relu) (R8/R13 form) --------------------
// 128-dim: self from fp16 mirror; SPLIT_OUT -> single fp16 h buffer.
template <int D, bool RELU, bool SPLIT_OUT>
__global__ void k_agg_post(const float* __restrict__ y,
                           const __half* __restrict__ y16,
                           const float* __restrict__ bias,
                           float* __restrict__ out,
                           __half* __restrict__ outf) {
    int gw = (blockIdx.x * blockDim.x + threadIdx.x) >> 5;
    int lane = threadIdx.x & 31;
    if (gw >= N_NODES) return;
    int beg = g_off[gw];
    int end = beg + g_deg[gw];

    if constexpr (D == 128) {
        uint2 su = __ldg((const uint2*)(y16 + (size_t)gw * 128) + lane);
        float2 sa = __half22float2(*(const __half2*)&su.x);
        float2 sb = __half22float2(*(const __half2*)&su.y);
        float4 acc = make_float4(sa.x, sa.y, sb.x, sb.y);
        float4 acc2 = make_float4(0.f, 0.f, 0.f, 0.f);
        int e = beg;
        for (; e + 3 < end; e += 4) {
            int s0 = g_srcs[e],     s1 = g_srcs[e + 1];
            int s2 = g_srcs[e + 2], s3 = g_srcs[e + 3];
            uint2 u0 = __ldg((const uint2*)(y16 + (size_t)s0 * 128) + lane);
            uint2 u1 = __ldg((const uint2*)(y16 + (size_t)s1 * 128) + lane);
            uint2 u2 = __ldg((const uint2*)(y16 + (size_t)s2 * 128) + lane);
            uint2 u3 = __ldg((const uint2*)(y16 + (size_t)s3 * 128) + lane);
            float2 a0 = __half22float2(*(const __half2*)&u0.x);
            float2 b0 = __half22float2(*(const __half2*)&u0.y);
            float2 a1 = __half22float2(*(const __half2*)&u1.x);
            float2 b1 = __half22float2(*(const __half2*)&u1.y);
            float2 a2 = __half22float2(*(const __half2*)&u2.x);
            float2 b2 = __half22float2(*(const __half2*)&u2.y);
            float2 a3 = __half22float2(*(const __half2*)&u3.x);
            float2 b3 = __half22float2(*(const __half2*)&u3.y);
            acc.x  += a0.x + a1.x; acc.y  += a0.y + a1.y;
            acc.z  += b0.x + b1.x; acc.w  += b0.y + b1.y;
            acc2.x += a2.x + a3.x; acc2.y += a2.y + a3.y;
            acc2.z += b2.x + b3.x; acc2.w += b2.y + b3.y;
        }
        for (; e < end; ++e) {
            int s = g_srcs[e];
            uint2 u = __ldg((const uint2*)(y16 + (size_t)s * 128) + lane);
            float2 a = __half22float2(*(const __half2*)&u.x);
            float2 b = __half22float2(*(const __half2*)&u.y);
            acc.x += a.x; acc.y += a.y; acc.z += b.x; acc.w += b.y;
        }
        acc.x += acc2.x; acc.y += acc2.y; acc.z += acc2.z; acc.w += acc2.w;
        float4 bb = __ldg((const float4*)bias + lane);
        acc.x += bb.x; acc.y += bb.y; acc.z += bb.z; acc.w += bb.w;
        if (RELU) {
            acc.x = fmaxf(acc.x, 0.f); acc.y = fmaxf(acc.y, 0.f);
            acc.z = fmaxf(acc.z, 0.f); acc.w = fmaxf(acc.w, 0.f);
        }
        if constexpr (SPLIT_OUT) {
            __half2 h0 = __floats2half2_rn(acc.x, acc.y);
            __half2 h1 = __floats2half2_rn(acc.z, acc.w);
            uint2 o;
            o.x = *(const unsigned*)&h0;
            o.y = *(const unsigned*)&h1;
            ((uint2*)(outf + (size_t)gw * 128))[lane] = o;
        } else {
            ((float4*)(out + (size_t)gw * 128))[lane] = acc;
        }
    } else {
        float2 acc = __ldg((const float2*)(y + (size_t)gw * 64) + lane);
        float2 acc2 = make_float2(0.f, 0.f);
        int e = beg;
        for (; e + 3 < end; e += 4) {
            int s0 = g_srcs[e],     s1 = g_srcs[e + 1];
            int s2 = g_srcs[e + 2], s3 = g_srcs[e + 3];
            unsigned u0 = __ldg((const unsigned*)(y16 + (size_t)s0 * 64) + lane);
            unsigned u1 = __ldg((const unsigned*)(y16 + (size_t)s1 * 64) + lane);
            unsigned u2 = __ldg((const unsigned*)(y16 + (size_t)s2 * 64) + lane);
            unsigned u3 = __ldg((const unsigned*)(y16 + (size_t)s3 * 64) + lane);
            float2 a0 = __half22float2(*(const __half2*)&u0);
            float2 a1 = __half22float2(*(const __half2*)&u1);
            float2 a2 = __half22float2(*(const __half2*)&u2);
            float2 a3 = __half22float2(*(const __half2*)&u3);
            acc.x  += a0.x + a1.x; acc.y  += a0.y + a1.y;
            acc2.x += a2.x + a3.x; acc2.y += a2.y + a3.y;
        }
        for (; e < end; ++e) {
            int s = g_srcs[e];
            unsigned u = __ldg((const unsigned*)(y16 + (size_t)s * 64) + lane);
            float2 a = __half22float2(*(const __half2*)&u);
            acc.x += a.x; acc.y += a.y;
        }
        acc.x += acc2.x; acc.y += acc2.y;
        float2 bb = __ldg((const float2*)bias + lane);
        acc.x += bb.x; acc.y += bb.y;
        if (RELU) { acc.x = fmaxf(acc.x, 0.f); acc.y = fmaxf(acc.y, 0.f); }
        ((float2*)(out + (size_t)gw * 64))[lane] = acc;
    }
}

// ---------------- launch ----------------
extern "C" void kernel_launch(void* const* d_in, const int* in_sizes, int n_in,
                              void* d_out, int out_size) {
    const float* x  = (const float*)d_in[0];
    const int*   ei = (const int*)d_in[1];
    const float* W1 = (const float*)d_in[2];
    const float* b1 = (const float*)d_in[3];
    const float* Wm = (const float*)d_in[4];
    const float* bm = (const float*)d_in[5];
    const float* W2 = (const float*)d_in[6];
    const float* b2 = (const float*)d_in[7];
    float* out = (float*)d_out;

    const int smem128 = (64 * 136 * 2 + 128 * 136 * 2) * 2;   // 104448
    const int smem64  = (128 * 136 * 2 + 128 * 72 * 2) * 2;   // 106496

    static bool initDone = false;
    static cudaStream_t s2 = nullptr;
    static cudaEvent_t evFork = nullptr, evJoin = nullptr;
    if (!initDone) {
        cudaFuncSetAttribute((const void*)k_gemm_p<128, false, false>,
                             cudaFuncAttributeMaxDynamicSharedMemorySize, smem128);
        cudaFuncSetAttribute((const void*)k_gemm_p<128, true, false>,
                             cudaFuncAttributeMaxDynamicSharedMemorySize, smem128);
        cudaFuncSetAttribute((const void*)k_gemm_p<64, true, true>,
                             cudaFuncAttributeMaxDynamicSharedMemorySize, smem64);
        cudaStreamCreateWithFlags(&s2, cudaStreamNonBlocking);
        cudaEventCreateWithFlags(&evFork, cudaEventDisableTiming);
        cudaEventCreateWithFlags(&evJoin, cudaEventDisableTiming);
        initDone = true;
    }

    float* bufY = nullptr; __half* bufY16 = nullptr; __half* bufHf = nullptr;
    __nv_bfloat16 *w1h, *w1l, *wmh, *wml, *w2h, *w2l;
    cudaGetSymbolAddress((void**)&bufY, g_bufY);
    cudaGetSymbolAddress((void**)&bufY16, g_bufY16);
    cudaGetSymbolAddress((void**)&bufHf, g_bufHf);
    cudaGetSymbolAddress((void**)&w1h, g_W1h); cudaGetSymbolAddress((void**)&w1l, g_W1l);
    cudaGetSymbolAddress((void**)&wmh, g_Wmh); cudaGetSymbolAddress((void**)&wml, g_Wml);
    cudaGetSymbolAddress((void**)&w2h, g_W2h); cudaGetSymbolAddress((void**)&w2l, g_W2l);

    const int aggBlocks = (N_NODES + 7) / 8;

    // ---- fork: Wm/W2 conversion + CSR build on s2 ----
    cudaEventRecord(evFork, 0);
    cudaStreamWaitEvent(s2, evFork, 0);

    k_wconv<<<(128 * 128 + 255) / 256, 256, 0, s2>>>(Wm, wmh, wml, 128 * 128);
    k_wconv<<<(128 * 64 + 255) / 256, 256, 0, s2>>>(W2, w2h, w2l, 128 * 64);
    k_zero_deg<<<(N_NODES + 255) / 256, 256, 0, s2>>>();
    k_hist<<<(N_EDGES + 255) / 256, 256, 0, s2>>>(ei);
    k_scan1<<<SCAN_NB, SCAN_B, 0, s2>>>();
    k_scan2<<<SCAN_NB, SCAN_B, 0, s2>>>();
    k_scatter<<<(N_EDGES + 255) / 256, 256, 0, s2>>>(ei);
    cudaEventRecord(evJoin, s2);

    // main stream: W1 conversion + layer-1 persistent GEMM (fp16-only out)
    k_wconv<<<(128 * 128 + 255) / 256, 256>>>(W1, w1h, w1l, 128 * 128);
    k_gemm_p<128, false, false><<<PGRID, 256, smem128>>>(
        x, nullptr, w1h, w1l, nullptr, bufY16);

    cudaStreamWaitEvent(0, evJoin, 0);

    // layer 1 agg (self from fp16) -> fp16 h
    k_agg_post<128, true, true><<<aggBlocks, 256>>>(
        nullptr, bufY16, b1, nullptr, bufHf);

    // layer 2 (A = fp16 h; fp16-only out)
    k_gemm_p<128, true, false><<<PGRID, 256, smem128>>>(
        nullptr, bufHf, wmh, wml, nullptr, bufY16);
    k_agg_post<128, true, true><<<aggBlocks, 256>>>(
        nullptr, bufY16, bm, nullptr, bufHf);

    // layer 3 (64-dim; fp32 + fp16 out)
    k_gemm_p<64, true, true><<<PGRID, 256, smem64>>>(
        nullptr, bufHf, w2h, w2l, bufY, bufY16);
    k_agg_post<64, false, false><<<aggBlocks, 256>>>(
        bufY, bufY16, b2, out, nullptr);

    (void)in_sizes; (void)n_in; (void)out_size;
}

// round 15
// speedup vs baseline: 1.5690x; 1.0298x over previous
#include <cuda_runtime.h>
#include <cuda_fp16.h>
#include <cuda_bf16.h>
#include <stdint.h>

#define N_NODES 100000
#define N_EDGES 1600000
#define DIM 128
#define SCAN_B 1024
#define SCAN_NB ((N_NODES + SCAN_B - 1) / SCAN_B)   // 98
#define PGRID 296   // persistent GEMM grid: 2 CTAs/SM

// ---------------- scratch (no allocations allowed) ----------------
__device__ int    g_deg[N_NODES];
__device__ int    g_off[N_NODES];
__device__ int    g_cur[N_NODES];
__device__ int2   g_span[N_NODES];                   // (beg, end)
__device__ int    g_bsums[SCAN_NB];
__device__ int    g_srcs[N_EDGES];
__device__ __half g_bufY16[(size_t)N_NODES * DIM];   // fp16 GEMM out (gather src)
__device__ __half g_bufHf[(size_t)N_NODES * DIM];    // fp16 h (next GEMM A)
__device__ __nv_bfloat16 g_W1h[128 * 128], g_W1l[128 * 128];
__device__ __nv_bfloat16 g_Wmh[128 * 128], g_Wml[128 * 128];
__device__ __nv_bfloat16 g_W2h[128 * 64],  g_W2l[128 * 64];

// ---------------- CSR construction ----------------
__global__ void k_zero_deg() {
    int i = blockIdx.x * blockDim.x + threadIdx.x;
    if (i < N_NODES) g_deg[i] = 0;
}

__global__ void k_hist(const int* __restrict__ ei) {
    int e = blockIdx.x * blockDim.x + threadIdx.x;
    if (e < N_EDGES) {
        int d = ei[N_EDGES + e];
        if (d >= 0 && d < N_NODES) atomicAdd(&g_deg[d], 1);
    }
}

__global__ void k_scan1() {
    __shared__ int s[SCAN_B];
    int tid = threadIdx.x;
    int i = blockIdx.x * SCAN_B + tid;
    int v = (i < N_NODES) ? g_deg[i] : 0;
    s[tid] = v;
    __syncthreads();
    #pragma unroll
    for (int d = 1; d < SCAN_B; d <<= 1) {
        int t = (tid >= d) ? s[tid - d] : 0;
        __syncthreads();
        s[tid] += t;
        __syncthreads();
    }
    if (i < N_NODES) g_off[i] = s[tid] - v;
    if (tid == SCAN_B - 1) g_bsums[blockIdx.x] = s[tid];
}

__global__ void k_scan2() {
    __shared__ int red[32];
    int tid = threadIdx.x;
    int v = (tid < (int)blockIdx.x && tid < SCAN_NB) ? g_bsums[tid] : 0;
    #pragma unroll
    for (int o = 16; o > 0; o >>= 1) v += __shfl_down_sync(0xffffffffu, v, o);
    if ((tid & 31) == 0) red[tid >> 5] = v;
    __syncthreads();
    if (tid < 32) {
        int r = (tid < (int)(blockDim.x >> 5)) ? red[tid] : 0;
        #pragma unroll
        for (int o = 16; o > 0; o >>= 1) r += __shfl_down_sync(0xffffffffu, r, o);
        if (tid == 0) red[0] = r;
    }
    __syncthreads();
    int base = red[0];
    int i = blockIdx.x * SCAN_B + tid;
    if (i < N_NODES) {
        int o = g_off[i] + base;
        g_off[i] = o;
        g_cur[i] = o;
        g_span[i] = make_int2(o, o + g_deg[i]);
    }
}

// scatter over edge range [start, start+count)
__global__ void k_scatter(const int* __restrict__ ei, int start, int count) {
    int e = blockIdx.x * blockDim.x + threadIdx.x + start;
    if (e < start + count) {
        int d = ei[N_EDGES + e];
        int s = ei[e];
        if (d >= 0 && d < N_NODES && s >= 0 && s < N_NODES) {
            int pos = atomicAdd(&g_cur[d], 1);
            g_srcs[pos] = s;
        }
    }
}

// ---------------- helpers ----------------
__device__ __forceinline__ unsigned cvta_s(const void* p) {
    return (unsigned)__cvta_generic_to_shared(p);
}
__device__ __forceinline__ void ldsm_x4(unsigned& r0, unsigned& r1,
                                        unsigned& r2, unsigned& r3, unsigned a) {
    asm volatile("ldmatrix.sync.aligned.m8n8.x4.shared.b16 {%0,%1,%2,%3}, [%4];"
                 : "=r"(r0), "=r"(r1), "=r"(r2), "=r"(r3) : "r"(a));
}
__device__ __forceinline__ void ldsm_x2t(unsigned& r0, unsigned& r1, unsigned a) {
    asm volatile("ldmatrix.sync.aligned.m8n8.x2.trans.shared.b16 {%0,%1}, [%2];"
                 : "=r"(r0), "=r"(r1) : "r"(a));
}
__device__ __forceinline__ void mma_bf16(float* c, unsigned a0, unsigned a1,
                                         unsigned a2, unsigned a3,
                                         unsigned b0, unsigned b1) {
    asm volatile(
        "mma.sync.aligned.m16n8k16.row.col.f32.bf16.bf16.f32 "
        "{%0,%1,%2,%3}, {%4,%5,%6,%7}, {%8,%9}, {%0,%1,%2,%3};"
        : "+f"(c[0]), "+f"(c[1]), "+f"(c[2]), "+f"(c[3])
        : "r"(a0), "r"(a1), "r"(a2), "r"(a3), "r"(b0), "r"(b1));
}
__device__ __forceinline__ unsigned pack_bf16(__nv_bfloat16 a, __nv_bfloat16 b) {
    __nv_bfloat162 p; p.x = a; p.y = b;
    return *reinterpret_cast<unsigned*>(&p);
}
__device__ __forceinline__ void bsplit(float f, __nv_bfloat16& h, __nv_bfloat16& l) {
    h = __float2bfloat16_rn(f);
    l = __float2bfloat16_rn(f - __bfloat162float(h));
}

// ---------------- W preconversion: fp32 -> bf16 hi/lo ----------------
__global__ void k_wconv(const float* __restrict__ W, __nv_bfloat16* __restrict__ Wh,
                        __nv_bfloat16* __restrict__ Wl, int n) {
    int i = blockIdx.x * blockDim.x + threadIdx.x;
    if (i < n) {
        float f = W[i];
        __nv_bfloat16 h, l;
        bsplit(f, h, l);
        Wh[i] = h; Wl[i] = l;
    }
}

// -------- GEMM mainloop+epilogue for one tile (8 warps) --------
template <int DOUT>
__device__ __forceinline__ void gemm_body(
    const __nv_bfloat16* sAh, const __nv_bfloat16* sAl,
    const __nv_bfloat16* sWh, const __nv_bfloat16* sWl,
    int wid, int lane, int rowBase, __half* __restrict__ Y16) {
    constexpr int LDA = 136;
    constexpr int LDB = DOUT + 8;
    int g = lane >> 2, tg = lane & 3;
    int rg, n0;
    if constexpr (DOUT == 128) { rg = wid >> 1; n0 = (wid & 1) * 64; }
    else                       { rg = wid;      n0 = 0; }
    int r0 = rg * 16;

    float acc[8][4];
    #pragma unroll
    for (int i = 0; i < 8; ++i)
        #pragma unroll
        for (int j = 0; j < 4; ++j) acc[i][j] = 0.f;

    int arow = r0 + (lane & 15);
    int acolo = (lane >> 4) * 8;
    unsigned aH = cvta_s(sAh) + (unsigned)((arow * LDA + acolo) * 2);
    unsigned aL = cvta_s(sAl) + (unsigned)((arow * LDA + acolo) * 2);
    int brow = lane & 15;
    unsigned bH = cvta_s(sWh) + (unsigned)((brow * LDB + n0) * 2);
    unsigned bL = cvta_s(sWl) + (unsigned)((brow * LDB + n0) * 2);

    #pragma unroll
    for (int ks = 0; ks < 8; ++ks) {
        int k0 = ks * 16;
        unsigned ah0, ah1, ah2, ah3, al0, al1, al2, al3;
        ldsm_x4(ah0, ah1, ah2, ah3, aH + (unsigned)(k0 * 2));
        ldsm_x4(al0, al1, al2, al3, aL + (unsigned)(k0 * 2));
        unsigned bkoff = (unsigned)(k0 * LDB * 2);
        #pragma unroll
        for (int nt = 0; nt < 8; ++nt) {
            unsigned noff = bkoff + (unsigned)(nt * 8 * 2);
            unsigned bh0, bh1, bl0, bl1;
            ldsm_x2t(bh0, bh1, bH + noff);
            ldsm_x2t(bl0, bl1, bL + noff);
            mma_bf16(acc[nt], ah0, ah1, ah2, ah3, bh0, bh1);
            mma_bf16(acc[nt], al0, al1, al2, al3, bh0, bh1);
            mma_bf16(acc[nt], ah0, ah1, ah2, ah3, bl0, bl1);
        }
    }

    int row0 = rowBase + r0 + g;
    int row1 = row0 + 8;
    #pragma unroll
    for (int nt = 0; nt < 8; ++nt) {
        int col = n0 + nt * 8 + tg * 2;
        if (row0 < N_NODES) {
            __half2 hh = __floats2half2_rn(acc[nt][0], acc[nt][1]);
            *(unsigned*)(Y16 + (size_t)row0 * DOUT + col) = *(const unsigned*)&hh;
        }
        if (row1 < N_NODES) {
            __half2 hh = __floats2half2_rn(acc[nt][2], acc[nt][3]);
            *(unsigned*)(Y16 + (size_t)row1 * DOUT + col) = *(const unsigned*)&hh;
        }
    }
}

// ---------------- Persistent GEMM: Y16 = A[N,128] @ W[128,DOUT] ------------
template <int DOUT, bool A_FP16>
__global__ void __launch_bounds__(256, 2)
k_gemm_p(const float* __restrict__ X, const __half* __restrict__ Xf,
         const __nv_bfloat16* __restrict__ Wh, const __nv_bfloat16* __restrict__ Wl,
         __half* __restrict__ Y16) {
    constexpr int TROWS = (DOUT == 128) ? 64 : 128;
    constexpr int LDA = 136;
    constexpr int LDB = DOUT + 8;
    extern __shared__ __nv_bfloat16 sm[];
    __nv_bfloat16* sAh = sm;
    __nv_bfloat16* sAl = sAh + TROWS * LDA;
    __nv_bfloat16* sWh = sAl + TROWS * LDA;
    __nv_bfloat16* sWl = sWh + 128 * LDB;

    int tid = threadIdx.x, wid = tid >> 5, lane = tid & 31;

    // W load once per CTA
    for (int i = tid; i < 128 * (DOUT / 8); i += 256) {
        int k = i / (DOUT / 8), n8 = i % (DOUT / 8);
        uint4 vh = __ldg((const uint4*)(Wh + (size_t)k * DOUT) + n8);
        uint4 vl = __ldg((const uint4*)(Wl + (size_t)k * DOUT) + n8);
        int off = k * LDB + n8 * 8;
        *(uint4*)(sWh + off) = vh;
        *(uint4*)(sWl + off) = vl;
    }

    const int numTiles = (N_NODES + TROWS - 1) / TROWS;
    for (int t = blockIdx.x; t < numTiles; t += gridDim.x) {
        int rowBase = t * TROWS;
        __syncthreads();
        if constexpr (A_FP16) {
            for (int i = tid; i < TROWS * 32; i += 256) {
                int r = i >> 5, c4 = i & 31;
                int row = rowBase + r;
                uint2 u = make_uint2(0, 0);
                if (row < N_NODES)
                    u = __ldg((const uint2*)(Xf + (size_t)row * 128) + c4);
                float2 f0 = __half22float2(*(const __half2*)&u.x);
                float2 f1 = __half22float2(*(const __half2*)&u.y);
                __nv_bfloat16 h0, h1, h2, h3, l0, l1, l2, l3;
                bsplit(f0.x, h0, l0); bsplit(f0.y, h1, l1);
                bsplit(f1.x, h2, l2); bsplit(f1.y, h3, l3);
                int off = r * LDA + c4 * 4;
                *(uint2*)(sAh + off) = make_uint2(pack_bf16(h0, h1), pack_bf16(h2, h3));
                *(uint2*)(sAl + off) = make_uint2(pack_bf16(l0, l1), pack_bf16(l2, l3));
            }
        } else {
            for (int i = tid; i < TROWS * 32; i += 256) {
                int r = i >> 5, c4 = i & 31;
                int row = rowBase + r;
                float4 v = make_float4(0.f, 0.f, 0.f, 0.f);
                if (row < N_NODES)
                    v = __ldg((const float4*)(X + (size_t)row * 128) + c4);
                __nv_bfloat16 h0, h1, h2, h3, l0, l1, l2, l3;
                bsplit(v.x, h0, l0); bsplit(v.y, h1, l1);
                bsplit(v.z, h2, l2); bsplit(v.w, h3, l3);
                int off = r * LDA + c4 * 4;
                *(uint2*)(sAh + off) = make_uint2(pack_bf16(h0, h1), pack_bf16(h2, h3));
                *(uint2*)(sAl + off) = make_uint2(pack_bf16(l0, l1), pack_bf16(l2, l3));
            }
        }
        __syncthreads();
        gemm_body<DOUT>(sAh, sAl, sWh, sWl, wid, lane, rowBase, Y16);
    }
}

// ---------- fused aggregate + bias (+relu); all terms from fp16 mirror -----
// 128-dim: writes fp16 h. 64-dim (final): writes fp32 out.
template <int D, bool RELU>
__global__ void k_agg_post(const __half* __restrict__ y16,
                           const float* __restrict__ bias,
                           float* __restrict__ out,
                           __half* __restrict__ outf) {
    int gw = (blockIdx.x * blockDim.x + threadIdx.x) >> 5;
    int lane = threadIdx.x & 31;
    if (gw >= N_NODES) return;
    int2 span = g_span[gw];
    int beg = span.x, end = span.y;

    if constexpr (D == 128) {
        uint2 su = __ldg((const uint2*)(y16 + (size_t)gw * 128) + lane);
        float2 sa = __half22float2(*(const __half2*)&su.x);
        float2 sb = __half22float2(*(const __half2*)&su.y);
        float4 acc = make_float4(sa.x, sa.y, sb.x, sb.y);
        float4 acc2 = make_float4(0.f, 0.f, 0.f, 0.f);
        int e = beg;
        for (; e + 3 < end; e += 4) {
            int s0 = g_srcs[e],     s1 = g_srcs[e + 1];
            int s2 = g_srcs[e + 2], s3 = g_srcs[e + 3];
            uint2 u0 = __ldg((const uint2*)(y16 + (size_t)s0 * 128) + lane);
            uint2 u1 = __ldg((const uint2*)(y16 + (size_t)s1 * 128) + lane);
            uint2 u2 = __ldg((const uint2*)(y16 + (size_t)s2 * 128) + lane);
            uint2 u3 = __ldg((const uint2*)(y16 + (size_t)s3 * 128) + lane);
            float2 a0 = __half22float2(*(const __half2*)&u0.x);
            float2 b0 = __half22float2(*(const __half2*)&u0.y);
            float2 a1 = __half22float2(*(const __half2*)&u1.x);
            float2 b1 = __half22float2(*(const __half2*)&u1.y);
            float2 a2 = __half22float2(*(const __half2*)&u2.x);
            float2 b2 = __half22float2(*(const __half2*)&u2.y);
            float2 a3 = __half22float2(*(const __half2*)&u3.x);
            float2 b3 = __half22float2(*(const __half2*)&u3.y);
            acc.x  += a0.x + a1.x; acc.y  += a0.y + a1.y;
            acc.z  += b0.x + b1.x; acc.w  += b0.y + b1.y;
            acc2.x += a2.x + a3.x; acc2.y += a2.y + a3.y;
            acc2.z += b2.x + b3.x; acc2.w += b2.y + b3.y;
        }
        for (; e < end; ++e) {
            int s = g_srcs[e];
            uint2 u = __ldg((const uint2*)(y16 + (size_t)s * 128) + lane);
            float2 a = __half22float2(*(const __half2*)&u.x);
            float2 b = __half22float2(*(const __half2*)&u.y);
            acc.x += a.x; acc.y += a.y; acc.z += b.x; acc.w += b.y;
        }
        acc.x += acc2.x; acc.y += acc2.y; acc.z += acc2.z; acc.w += acc2.w;
        float4 bb = __ldg((const float4*)bias + lane);
        acc.x += bb.x; acc.y += bb.y; acc.z += bb.z; acc.w += bb.w;
        if (RELU) {
            acc.x = fmaxf(acc.x, 0.f); acc.y = fmaxf(acc.y, 0.f);
            acc.z = fmaxf(acc.z, 0.f); acc.w = fmaxf(acc.w, 0.f);
        }
        __half2 h0 = __floats2half2_rn(acc.x, acc.y);
        __half2 h1 = __floats2half2_rn(acc.z, acc.w);
        uint2 o;
        o.x = *(const unsigned*)&h0;
        o.y = *(const unsigned*)&h1;
        ((uint2*)(outf + (size_t)gw * 128))[lane] = o;
    } else {
        unsigned su = __ldg((const unsigned*)(y16 + (size_t)gw * 64) + lane);
        float2 acc = __half22float2(*(const __half2*)&su);
        float2 acc2 = make_float2(0.f, 0.f);
        int e = beg;
        for (; e + 3 < end; e += 4) {
            int s0 = g_srcs[e],     s1 = g_srcs[e + 1];
            int s2 = g_srcs[e + 2], s3 = g_srcs[e + 3];
            unsigned u0 = __ldg((const unsigned*)(y16 + (size_t)s0 * 64) + lane);
            unsigned u1 = __ldg((const unsigned*)(y16 + (size_t)s1 * 64) + lane);
            unsigned u2 = __ldg((const unsigned*)(y16 + (size_t)s2 * 64) + lane);
            unsigned u3 = __ldg((const unsigned*)(y16 + (size_t)s3 * 64) + lane);
            float2 a0 = __half22float2(*(const __half2*)&u0);
            float2 a1 = __half22float2(*(const __half2*)&u1);
            float2 a2 = __half22float2(*(const __half2*)&u2);
            float2 a3 = __half22float2(*(const __half2*)&u3);
            acc.x  += a0.x + a1.x; acc.y  += a0.y + a1.y;
            acc2.x += a2.x + a3.x; acc2.y += a2.y + a3.y;
        }
        for (; e < end; ++e) {
            int s = g_srcs[e];
            unsigned u = __ldg((const unsigned*)(y16 + (size_t)s * 64) + lane);
            float2 a = __half22float2(*(const __half2*)&u);
            acc.x += a.x; acc.y += a.y;
        }
        acc.x += acc2.x; acc.y += acc2.y;
        float2 bb = __ldg((const float2*)bias + lane);
        acc.x += bb.x; acc.y += bb.y;
        ((float2*)(out + (size_t)gw * 64))[lane] = acc;
    }
}

// ---------------- launch ----------------
extern "C" void kernel_launch(void* const* d_in, const int* in_sizes, int n_in,
                              void* d_out, int out_size) {
    const float* x  = (const float*)d_in[0];
    const int*   ei = (const int*)d_in[1];
    const float* W1 = (const float*)d_in[2];
    const float* b1 = (const float*)d_in[3];
    const float* Wm = (const float*)d_in[4];
    const float* bm = (const float*)d_in[5];
    const float* W2 = (const float*)d_in[6];
    const float* b2 = (const float*)d_in[7];
    float* out = (float*)d_out;

    const int smem128 = (64 * 136 * 2 + 128 * 136 * 2) * 2;   // 104448
    const int smem64  = (128 * 136 * 2 + 128 * 72 * 2) * 2;   // 106496

    static bool initDone = false;
    static cudaStream_t s2 = nullptr;
    static cudaEvent_t evFork = nullptr, evScan = nullptr, evJoin = nullptr;
    if (!initDone) {
        cudaFuncSetAttribute((const void*)k_gemm_p<128, false>,
                             cudaFuncAttributeMaxDynamicSharedMemorySize, smem128);
        cudaFuncSetAttribute((const void*)k_gemm_p<128, true>,
                             cudaFuncAttributeMaxDynamicSharedMemorySize, smem128);
        cudaFuncSetAttribute((const void*)k_gemm_p<64, true>,
                             cudaFuncAttributeMaxDynamicSharedMemorySize, smem64);
        cudaStreamCreateWithFlags(&s2, cudaStreamNonBlocking);
        cudaEventCreateWithFlags(&evFork, cudaEventDisableTiming);
        cudaEventCreateWithFlags(&evScan, cudaEventDisableTiming);
        cudaEventCreateWithFlags(&evJoin, cudaEventDisableTiming);
        initDone = true;
    }

    __half* bufY16 = nullptr; __half* bufHf = nullptr;
    __nv_bfloat16 *w1h, *w1l, *wmh, *wml, *w2h, *w2l;
    cudaGetSymbolAddress((void**)&bufY16, g_bufY16);
    cudaGetSymbolAddress((void**)&bufHf, g_bufHf);
    cudaGetSymbolAddress((void**)&w1h, g_W1h); cudaGetSymbolAddress((void**)&w1l, g_W1l);
    cudaGetSymbolAddress((void**)&wmh, g_Wmh); cudaGetSymbolAddress((void**)&wml, g_Wml);
    cudaGetSymbolAddress((void**)&w2h, g_W2h); cudaGetSymbolAddress((void**)&w2l, g_W2l);

    const int aggBlocks = (N_NODES + 7) / 8;
    const int E_HALF = N_EDGES / 2;
    const int scatB = (E_HALF + 255) / 256;

    // ---- fork: Wm/W2 conversion + CSR build (hist/scan + scatter half A) ---
    cudaEventRecord(evFork, 0);
    cudaStreamWaitEvent(s2, evFork, 0);

    k_wconv<<<(128 * 128 + 255) / 256, 256, 0, s2>>>(Wm, wmh, wml, 128 * 128);
    k_wconv<<<(128 * 64 + 255) / 256, 256, 0, s2>>>(W2, w2h, w2l, 128 * 64);
    k_zero_deg<<<(N_NODES + 255) / 256, 256, 0, s2>>>();
    k_hist<<<(N_EDGES + 255) / 256, 256, 0, s2>>>(ei);
    k_scan1<<<SCAN_NB, SCAN_B, 0, s2>>>();
    k_scan2<<<SCAN_NB, SCAN_B, 0, s2>>>();
    cudaEventRecord(evScan, s2);
    k_scatter<<<scatB, 256, 0, s2>>>(ei, 0, E_HALF);              // half A
    cudaEventRecord(evJoin, s2);

    // main stream: W1 conversion + layer-1 persistent GEMM, then scatter half B
    k_wconv<<<(128 * 128 + 255) / 256, 256>>>(W1, w1h, w1l, 128 * 128);
    k_gemm_p<128, false><<<PGRID, 256, smem128>>>(
        x, nullptr, w1h, w1l, bufY16);
    cudaStreamWaitEvent(0, evScan, 0);
    k_scatter<<<scatB, 256>>>(ei, E_HALF, N_EDGES - E_HALF);      // half B
    cudaStreamWaitEvent(0, evJoin, 0);

    // layer 1 agg -> fp16 h
    k_agg_post<128, true><<<aggBlocks, 256>>>(bufY16, b1, nullptr, bufHf);

    // layer 2
    k_gemm_p<128, true><<<PGRID, 256, smem128>>>(
        nullptr, bufHf, wmh, wml, bufY16);
    k_agg_post<128, true><<<aggBlocks, 256>>>(bufY16, bm, nullptr, bufHf);

    // layer 3 (64-dim, fp16-only)
    k_gemm_p<64, true><<<PGRID, 256, smem64>>>(
        nullptr, bufHf, w2h, w2l, bufY16);
    k_agg_post<64, false><<<aggBlocks, 256>>>(bufY16, b2, out, nullptr);

    (void)in_sizes; (void)n_in; (void)out_size;
}